// round 2
// baseline (speedup 1.0000x reference)
#include <cuda_runtime.h>

#define NB 2
#define AB 1344
#define LB 96
#define ATOMS 14
#define DB 128
#define HB 8
#define DEPTH 3
#define RB (NB*AB)      /* 2688 rows */
#define EB (HB*DB)      /* 1024 cols */
#define WORDS (AB/32)   /* 42 */

// ---------------- scratch (device globals; no allocation allowed) ----------------
__device__ float g_fp[RB*EB];          // projected features (N,A,H,D)  ~11MB
__device__ float g_x0[RB*DB];          // ping
__device__ float g_x1[RB*DB];          // pong
__device__ float g_src[NB*HB*AB];
__device__ float g_tag[NB*HB*AB];
__device__ float g_es [NB*HB*AB];      // exp(src)
__device__ float g_es2[NB*HB*AB];      // exp(0.2*src)
__device__ float g_P  [NB*HB*AB];      // exp(tag)
__device__ float g_Q  [NB*HB*AB];      // exp(0.2*tag)
__device__ float g_diag[NB*HB*AB];
__device__ unsigned g_ebits[NB*AB*WORDS];

// ---------------- pack edge_mask (int32 0/1 words) -> bits ----------------
__global__ void pack_edges_k(const unsigned int* __restrict__ em) {
    int w = blockIdx.x * 8 + (threadIdx.x >> 5);
    int lane = threadIdx.x & 31;
    unsigned int v = em[(size_t)w * 32 + lane];
    unsigned m = __ballot_sync(0xffffffffu, v != 0u);
    if (lane == 0) g_ebits[w] = m;
}

// ---------------- GEMM: fp = X (2688x128) * W^T (1024x128), masked ----------------
// block tile 64x128, K-tile 32, 256 threads, thread tile 4x8
__global__ void gemm_fp_k(const float* __restrict__ X, const float* __restrict__ W,
                          const int* __restrict__ mask) {
    __shared__ float As[32][68];    // [k][row], padded
    __shared__ float Bs[32][132];   // [k][col]
    int tid = threadIdx.x;
    int tx = tid & 15, ty = tid >> 4;
    int rowBase = blockIdx.x * 64;
    int colBase = blockIdx.y * 128;

    float acc[4][8];
#pragma unroll
    for (int i = 0; i < 4; i++)
#pragma unroll
        for (int j = 0; j < 8; j++) acc[i][j] = 0.f;

    for (int k0 = 0; k0 < 128; k0 += 32) {
#pragma unroll
        for (int i = 0; i < 8; i++) {
            int e = tid + i * 256;          // 2048 elements
            int r = e >> 5, k = e & 31;
            As[k][r] = X[(rowBase + r) * 128 + k0 + k];
        }
#pragma unroll
        for (int i = 0; i < 16; i++) {
            int e = tid + i * 256;          // 4096 elements
            int c = e >> 5, k = e & 31;
            Bs[k][c] = W[(colBase + c) * 128 + k0 + k];
        }
        __syncthreads();
#pragma unroll
        for (int kk = 0; kk < 32; kk++) {
            float4 a4 = *(const float4*)&As[kk][ty * 4];
            float4 b0 = *(const float4*)&Bs[kk][tx * 8];
            float4 b1 = *(const float4*)&Bs[kk][tx * 8 + 4];
            float a[4] = {a4.x, a4.y, a4.z, a4.w};
            float b[8] = {b0.x, b0.y, b0.z, b0.w, b1.x, b1.y, b1.z, b1.w};
#pragma unroll
            for (int i = 0; i < 4; i++)
#pragma unroll
                for (int j = 0; j < 8; j++) acc[i][j] += a[i] * b[j];
        }
        __syncthreads();
    }
#pragma unroll
    for (int i = 0; i < 4; i++) {
        int r = rowBase + ty * 4 + i;
        float m = (mask[r] != 0) ? 1.f : 0.f;
        float4 v0 = make_float4(acc[i][0]*m, acc[i][1]*m, acc[i][2]*m, acc[i][3]*m);
        float4 v1 = make_float4(acc[i][4]*m, acc[i][5]*m, acc[i][6]*m, acc[i][7]*m);
        float* dst = &g_fp[(size_t)r * EB + colBase + tx * 8];
        *(float4*)dst = v0;
        *(float4*)(dst + 4) = v1;
    }
}

// ---------------- src/tag scores + exps ----------------
// block per (n,a), 8 warps = 8 heads
__global__ void scores_k(const float* __restrict__ ssrc, const float* __restrict__ stag) {
    int b = blockIdx.x;                  // row = n*AB + a
    int n = b / AB, a = b % AB;
    int wid = threadIdx.x >> 5, lane = threadIdx.x & 31;
    const float* fprow = &g_fp[(size_t)b * EB + wid * DB];
    const float* ws = &ssrc[wid * DB];
    const float* wt = &stag[wid * DB];
    float ps = 0.f, pt = 0.f;
#pragma unroll
    for (int i = 0; i < 4; i++) {
        float v = fprow[lane + i * 32];
        ps += v * ws[lane + i * 32];
        pt += v * wt[lane + i * 32];
    }
#pragma unroll
    for (int o = 16; o; o >>= 1) {
        ps += __shfl_xor_sync(0xffffffffu, ps, o);
        pt += __shfl_xor_sync(0xffffffffu, pt, o);
    }
    if (lane == 0) {
        int idx = (n * HB + wid) * AB + a;
        g_src[idx] = ps;
        g_tag[idx] = pt;
        g_es [idx] = __expf(ps);
        g_es2[idx] = __expf(0.2f * ps);
        g_P  [idx] = __expf(pt);
        g_Q  [idx] = __expf(0.2f * pt);
    }
}

// ---------------- diagonal attention coefficient ----------------
// grid: N*H*(A/16), 256 threads (8 warps, each warp handles 2 rows)
#define ATILE 16
__global__ void attn_k() {
    __shared__ float sT[AB], sP[AB], sQ[AB];
    __shared__ unsigned sE[ATILE][WORDS];
    int b = blockIdx.x;
    int atile = b % (AB / ATILE);
    int nh = b / (AB / ATILE);
    int h = nh % HB, n = nh / HB;
    int tid = threadIdx.x;
    int base = (n * HB + h) * AB;
    for (int j = tid; j < AB; j += 256) {
        sT[j] = g_tag[base + j];
        sP[j] = g_P[base + j];
        sQ[j] = g_Q[base + j];
    }
    int a0 = atile * ATILE;
    for (int w = tid; w < ATILE * WORDS; w += 256) {
        int rr = w / WORDS, ww = w % WORDS;
        sE[rr][ww] = g_ebits[(n * AB + a0 + rr) * WORDS + ww];
    }
    __syncthreads();
    int wid = tid >> 5, lane = tid & 31;
    unsigned lmask = 1u << lane;
#pragma unroll
    for (int rr = wid; rr < ATILE; rr += 8) {
        int a = a0 + rr;
        float s = g_src[base + a];
        float ns = -s;
        float sumP = 0.f, sumQ = 0.f;
#pragma unroll 6
        for (int it = 0; it < WORDS; it++) {
            unsigned wbits = sE[rr][it];
            int j = it * 32 + lane;
            float t = sT[j];
            if (wbits & lmask) {
                if (t > ns) sumP += sP[j];
                else        sumQ += sQ[j];
            }
        }
#pragma unroll
        for (int o = 16; o; o >>= 1) {
            sumP += __shfl_xor_sync(0xffffffffu, sumP, o);
            sumQ += __shfl_xor_sync(0xffffffffu, sumQ, o);
        }
        if (lane == 0) {
            float es = g_es[base + a], es2 = g_es2[base + a];
            float S = es * sumP + es2 * sumQ;
            unsigned selfb = sE[rr][a >> 5] & (1u << (a & 31));
            float num = 0.f;
            if (selfb) {
                float t = sT[a];
                num = (s + t > 0.f) ? es * sP[a] : es2 * sQ[a];
            }
            g_diag[base + a] = num / S;
        }
    }
}

// ---------------- epilogue: fo = diag*fp -> LN -> +skip -> head mean -> +bias ----------------
__device__ __forceinline__ float blockSum128(float v, float* red) {
#pragma unroll
    for (int o = 16; o; o >>= 1) v += __shfl_xor_sync(0xffffffffu, v, o);
    int wid = threadIdx.x >> 5, lane = threadIdx.x & 31;
    __syncthreads();
    if (lane == 0) red[wid] = v;
    __syncthreads();
    return red[0] + red[1] + red[2] + red[3];
}

__global__ void epi_k(const float* __restrict__ xin, float* __restrict__ xout,
                      const float* __restrict__ lng, const float* __restrict__ lnb,
                      const float* __restrict__ bias) {
    __shared__ float red[4];
    int b = blockIdx.x;                  // n*AB + a
    int n = b / AB, a = b % AB;
    int d = threadIdx.x;                 // 128 threads
    const float* fpb = &g_fp[(size_t)b * EB];
    float gd = lng[d], bd = lnb[d];
    float acc = 0.f;
#pragma unroll
    for (int h = 0; h < HB; h++) {
        float dg = g_diag[(n * HB + h) * AB + a];
        float v = dg * fpb[h * DB + d];
        float mu = blockSum128(v, red) * (1.f / 128.f);
        float dv = v - mu;
        float var = blockSum128(dv * dv, red) * (1.f / 128.f);
        float rstd = rsqrtf(var + 1e-5f);
        acc += dv * rstd * gd + bd;
    }
    float fin = xin[(size_t)b * DB + d];
    xout[(size_t)b * DB + d] = acc * 0.125f + fin + bias[d];
}

// ---------------- readout: mask + sum 14 atoms per residue ----------------
__global__ void readout_k(const float* __restrict__ x, const int* __restrict__ mask,
                          float* __restrict__ out) {
    int b = blockIdx.x;                  // n*LB + l
    int n = b / LB, l = b % LB;
    int d = threadIdx.x;
    float s = 0.f;
#pragma unroll
    for (int t = 0; t < ATOMS; t++) {
        int a = l * ATOMS + t;
        if (mask[n * AB + a] != 0) s += x[(size_t)(n * AB + a) * DB + d];
    }
    out[(size_t)b * DB + d] = s;
}

// ---------------- launch ----------------
extern "C" void kernel_launch(void* const* d_in, const int* in_sizes, int n_in,
                              void* d_out, int out_size) {
    const float*        feats = (const float*)d_in[0];
    const int*          mask  = (const int*)d_in[1];
    const unsigned int* emask = (const unsigned int*)d_in[2];
    const float*        W     = (const float*)d_in[3];
    const float*        ssrc  = (const float*)d_in[4];
    const float*        stag  = (const float*)d_in[5];
    const float*        bias  = (const float*)d_in[6];
    const float*        lng   = (const float*)d_in[7];
    const float*        lnb   = (const float*)d_in[8];
    float* out = (float*)d_out;

    float *px0 = nullptr, *px1 = nullptr;
    cudaGetSymbolAddress((void**)&px0, g_x0);
    cudaGetSymbolAddress((void**)&px1, g_x1);

    pack_edges_k<<<(NB * AB * WORDS) / 8, 256>>>(emask);

    const float* xin = feats;
    float* bufs[2] = {px0, px1};
    for (int l = 0; l < DEPTH; l++) {
        float* xout = bufs[l & 1];
        gemm_fp_k<<<dim3(RB / 64, EB / 128), 256>>>(xin, W + (size_t)l * EB * DB, mask);
        scores_k<<<RB, 256>>>(ssrc + l * HB * DB, stag + l * HB * DB);
        attn_k<<<NB * HB * (AB / ATILE), 256>>>();
        epi_k<<<RB, 128>>>(xin, xout, lng + l * DB, lnb + l * DB, bias + l * DB);
        xin = xout;
    }
    readout_k<<<NB * LB, 128>>>(xin, mask, out);
}